// round 1
// baseline (speedup 1.0000x reference)
#include <cuda_runtime.h>
#include <stdint.h>
#include <math.h>

// Problem constants
#define NBATCH 4
#define PREK   1024
#define NBUCK  65536      // 16-bit buckets of float bits (scores are positive)
#define CAP    4096       // candidate capacity per batch
#define MAXN   262144     // >= 200000
#define NEGBIG (-1e9f)

// ---------------- device scratch (no allocations allowed) ----------------
__device__ float              g_boxes[MAXN * 7];          // decoded boxes per point
__device__ unsigned           g_sbits[MAXN];              // score as ordered uint
__device__ int                g_hist[NBATCH * NBUCK];     // per-batch histogram
__device__ int                g_cut[NBATCH];              // cutoff bucket
__device__ int                g_cnt[NBATCH];              // candidate counters
__device__ unsigned long long g_cand[NBATCH * CAP];       // (score_bits<<32)|(~idx)
__device__ float              g_vals[NBATCH * PREK];      // top-k scores
__device__ float              g_box7[NBATCH * PREK * 7];  // gathered boxes
__device__ float              g_x1[NBATCH * PREK], g_x2[NBATCH * PREK];
__device__ float              g_y1[NBATCH * PREK], g_y2[NBATCH * PREK];
__device__ float              g_ar[NBATCH * PREK];
__device__ unsigned           g_rows[NBATCH * PREK * 32]; // suppression bitmask rows
__device__ unsigned           g_rowAny[NBATCH * 32];      // which rows have any overlap

// ---------------- K0: zero scratch that must start at 0 each replay -------
__global__ void k_zero() {
    int i = blockIdx.x * blockDim.x + threadIdx.x;
    if (i < NBATCH * NBUCK) g_hist[i] = 0;
    if (i < NBATCH)         g_cnt[i]  = 0;
    if (i < NBATCH * 32)    g_rowAny[i] = 0;
}

// ---------------- K1: per-point head (GEMV + decode + histogram) ----------
__global__ __launch_bounds__(256) void k_head(
    const float* __restrict__ feat, const int* __restrict__ bidx,
    const int* __restrict__ coor,
    const float* __restrict__ Wc, const float* __restrict__ bc,
    const float* __restrict__ Wr, const float* __restrict__ br, int n)
{
    int lane  = threadIdx.x & 31;
    int warp  = (blockIdx.x * blockDim.x + threadIdx.x) >> 5;
    int nwarp = (gridDim.x * blockDim.x) >> 5;
    int c0 = lane * 8;

    // per-lane weight slice in registers, reused across all points of this warp
    float wc0[8], wc1[8], wr[9][8];
#pragma unroll
    for (int i = 0; i < 8; i++) {
        wc0[i] = Wc[(c0 + i) * 2 + 0];
        wc1[i] = Wc[(c0 + i) * 2 + 1];
#pragma unroll
        for (int o = 0; o < 9; o++) wr[o][i] = Wr[(c0 + i) * 9 + o];
    }
    float bc0 = bc[0], bc1 = bc[1];
    float brr[9];
#pragma unroll
    for (int o = 0; o < 9; o++) brr[o] = br[o];

    for (int p = warp; p < n; p += nwarp) {
        const float4* f4 = reinterpret_cast<const float4*>(feat + (size_t)p * 256);
        float4 A = f4[2 * lane];
        float4 B = f4[2 * lane + 1];
        float fv[8] = {A.x, A.y, A.z, A.w, B.x, B.y, B.z, B.w};

        float acc[11];
#pragma unroll
        for (int o = 0; o < 11; o++) acc[o] = 0.f;
#pragma unroll
        for (int i = 0; i < 8; i++) {
            acc[0] += fv[i] * wc0[i];
            acc[1] += fv[i] * wc1[i];
#pragma unroll
            for (int o = 0; o < 9; o++) acc[2 + o] += fv[i] * wr[o][i];
        }
#pragma unroll
        for (int off = 16; off >= 1; off >>= 1)
#pragma unroll
            for (int o = 0; o < 11; o++)
                acc[o] += __shfl_xor_sync(0xffffffffu, acc[o], off);

        if (lane == 0) {
            float l0 = acc[0] + bc0, l1 = acc[1] + bc1;
            float conf = 1.f / (1.f + expf(l0 - l1));      // softmax prob of class 1
            float r0 = acc[2] + brr[0], r1 = acc[3] + brr[1], r2 = acc[4] + brr[2];
            float r3 = acc[5] + brr[3], r4 = acc[6] + brr[4], r5 = acc[7] + brr[5];
            float r6 = acc[8] + brr[6], r7 = acc[9] + brr[7], r8 = acc[10] + brr[8];
            float scr  = 1.f / (1.f + expf(-r8));
            float score = conf * scr;                       // in (0,1): positive

            float cx = (float)coor[2 * p]     * 0.8f + r0;  // VOXEL_SIZE*STRIDE
            float cy = (float)coor[2 * p + 1] * 0.8f + r1;
            float L  = expf(fminf(fmaxf(r3, -6.f), 6.f));
            float Wd = expf(fminf(fmaxf(r4, -6.f), 6.f));
            float H  = expf(fminf(fmaxf(r5, -6.f), 6.f));
            float ang = atan2f(r6, r7);

            float* bp = g_boxes + (size_t)p * 7;
            bp[0] = cx; bp[1] = cy; bp[2] = r2;
            bp[3] = L;  bp[4] = Wd; bp[5] = H; bp[6] = ang;

            unsigned sb = __float_as_uint(score);
            g_sbits[p] = sb;
            atomicAdd(&g_hist[bidx[p] * NBUCK + (sb >> 16)], 1);
        }
    }
}

// ---------------- K2: per-batch cutoff bucket from histogram --------------
__global__ __launch_bounds__(256) void k_cutoff() {
    int b = blockIdx.x, t = threadIdx.x;             // 256 threads, 256 buckets each
    const int4* h4 = reinterpret_cast<const int4*>(g_hist + b * NBUCK + t * 256);
    int s = 0;
#pragma unroll 8
    for (int i = 0; i < 64; i++) { int4 v = h4[i]; s += v.x + v.y + v.z + v.w; }
    __shared__ int cs[256];
    __shared__ int Sarr[257];
    cs[t] = s;
    __syncthreads();
    int S = 0;
    for (int u = t; u < 256; u++) S += cs[u];        // suffix sum (buckets >= t*256)
    Sarr[t] = S;
    if (t == 0) Sarr[256] = 0;
    __syncthreads();
    if (S >= PREK && Sarr[t + 1] < PREK) {
        int running = Sarr[t + 1];
        int cut = t * 256;
        for (int bk = t * 256 + 255; bk >= t * 256; --bk) {
            running += g_hist[b * NBUCK + bk];
            if (running >= PREK) { cut = bk; break; }
        }
        g_cut[b] = cut;
    }
    if (t == 0 && Sarr[0] < PREK) g_cut[b] = 0;      // fewer than PREK points
}

// ---------------- K3: compact candidates >= cutoff bucket -----------------
__global__ void k_compact(const int* __restrict__ bidx, int n) {
    int i = blockIdx.x * blockDim.x + threadIdx.x;
    if (i >= n) return;
    int b = bidx[i];
    unsigned sb = g_sbits[i];
    if ((int)(sb >> 16) >= g_cut[b]) {
        int pos = atomicAdd(&g_cnt[b], 1);
        if (pos < CAP)
            g_cand[b * CAP + pos] =
                ((unsigned long long)sb << 32) |
                (unsigned long long)(0xFFFFFFFFu - (unsigned)i); // smaller idx wins ties
    }
}

// ---------------- K4: per-batch bitonic sort + gather top-1024 ------------
__global__ __launch_bounds__(1024) void k_sort(int n) {
    __shared__ unsigned long long sk[CAP];
    int b = blockIdx.x, t = threadIdx.x;
    int cnt = g_cnt[b]; if (cnt > CAP) cnt = CAP;
#pragma unroll
    for (int r = 0; r < CAP / 1024; r++) {
        int i = t + r * 1024;
        sk[i] = (i < cnt) ? g_cand[b * CAP + i] : 0ULL;
    }
    __syncthreads();
    for (int k = 2; k <= CAP; k <<= 1) {
        for (int j = k >> 1; j > 0; j >>= 1) {
#pragma unroll
            for (int r = 0; r < CAP / 1024; r++) {
                int i = t + r * 1024;
                int l = i ^ j;
                if (l > i) {
                    unsigned long long A = sk[i], B = sk[l];
                    bool desc = ((i & k) == 0);
                    if (desc ? (A < B) : (A > B)) { sk[i] = B; sk[l] = A; }
                }
            }
            __syncthreads();
        }
    }
    if (t < PREK) {
        unsigned long long key = sk[t];
        unsigned idx = 0xFFFFFFFFu - (unsigned)(key & 0xFFFFFFFFull);
        float val = __uint_as_float((unsigned)(key >> 32));
        bool ok = (key != 0ULL) && (idx < (unsigned)n);
        float bx[7];
        if (ok) {
            const float* p = g_boxes + (size_t)idx * 7;
#pragma unroll
            for (int c = 0; c < 7; c++) bx[c] = p[c];
        } else {
#pragma unroll
            for (int c = 0; c < 7; c++) bx[c] = 0.f;
            val = NEGBIG;
        }
        int o = b * PREK + t;
        g_vals[o] = val;
#pragma unroll
        for (int c = 0; c < 7; c++) g_box7[o * 7 + c] = bx[c];
        float hx = bx[3] * 0.5f, hy = bx[4] * 0.5f;
        g_x1[o] = bx[0] - hx; g_x2[o] = bx[0] + hx;
        g_y1[o] = bx[1] - hy; g_y2[o] = bx[1] + hy;
        g_ar[o] = bx[3] * bx[4];
    }
}

// ---------------- K5: suppression bitmask rows (fully parallel) -----------
__global__ void k_iou() {
    int tid = blockIdx.x * blockDim.x + threadIdx.x;
    if (tid >= NBATCH * PREK * 8) return;
    int b   = tid >> 13;          // /(1024*8)
    int rem = tid & 8191;
    int i   = rem >> 3;
    int c   = rem & 7;            // 128-column chunk
    int o = b * PREK;
    float x1 = g_x1[o + i], x2 = g_x2[o + i];
    float y1 = g_y1[o + i], y2 = g_y2[o + i], ar = g_ar[o + i];
    unsigned w0 = 0, w1 = 0, w2 = 0, w3 = 0;
    int j0 = c * 128;
#pragma unroll 4
    for (int jj = 0; jj < 128; jj++) {
        int j = j0 + jj;
        if (j <= i) continue;
        float ix = fmaxf(fminf(x2, g_x2[o + j]) - fmaxf(x1, g_x1[o + j]), 0.f);
        float iy = fmaxf(fminf(y2, g_y2[o + j]) - fmaxf(y1, g_y1[o + j]), 0.f);
        float inter = ix * iy;
        float uni = ar + g_ar[o + j] - inter;
        float iou = inter / fmaxf(uni, 1e-6f);
        if (iou > 0.1f) {
            unsigned bit = 1u << (jj & 31);
            if      (jj < 32) w0 |= bit;
            else if (jj < 64) w1 |= bit;
            else if (jj < 96) w2 |= bit;
            else              w3 |= bit;
        }
    }
    unsigned* rp = g_rows + ((size_t)(o + i)) * 32 + c * 4;
    rp[0] = w0; rp[1] = w1; rp[2] = w2; rp[3] = w3;
    if (w0 | w1 | w2 | w3)
        atomicOr(&g_rowAny[b * 32 + (i >> 5)], 1u << (i & 31));
}

// ---------------- K6: sparse sequential NMS scan + output -----------------
__global__ __launch_bounds__(1024) void k_nms_out(float* __restrict__ out, int out_size) {
    __shared__ unsigned supp[32];
    int b = blockIdx.x, t = threadIdx.x;
    if (t < 32) {                               // warp 0: greedy scan over sparse rows
        unsigned sup = 0;
        unsigned myAny = g_rowAny[b * 32 + t];
        for (int w = 0; w < 32; w++) {
            unsigned aw = __shfl_sync(0xffffffffu, myAny, w);  // uniform
            while (aw) {
                int bit = __ffs(aw) - 1;
                aw &= aw - 1;
                int i = w * 32 + bit;
                unsigned sw = __shfl_sync(0xffffffffu, sup, i >> 5);
                if (!((sw >> (i & 31)) & 1u))   // row i kept -> suppress its overlaps
                    sup |= g_rows[((size_t)(b * PREK + i)) * 32 + t];
            }
        }
        supp[t] = sup;
    }
    __syncthreads();
    int o = b * PREK + t;
    float val = g_vals[o];
    bool valid = val > -5e8f;
    bool kp = valid && !((supp[t >> 5] >> (t & 31)) & 1u);
    float m = kp ? 1.f : 0.f;
    size_t base = (size_t)o * 8;
#pragma unroll
    for (int c = 0; c < 7; c++)
        if ((int)(base + c) < out_size) out[base + c] = g_box7[o * 7 + c] * m;
    if ((int)(base + 7) < out_size) out[base + 7] = val * m;
    size_t lbOff = (size_t)NBATCH * PREK * 8 + o;   // labels: argmax over 1 col = 0
    if ((int)lbOff < out_size) out[lbOff] = 0.f;
    size_t kpOff = (size_t)NBATCH * PREK * 9 + o;   // keep mask
    if ((int)kpOff < out_size) out[kpOff] = m;
}

// ---------------- launch ----------------
extern "C" void kernel_launch(void* const* d_in, const int* in_sizes, int n_in,
                              void* d_out, int out_size) {
    const float* feat = (const float*)d_in[0];
    const int*   bidx = (const int*)  d_in[1];
    const int*   coor = (const int*)  d_in[2];
    const float* Wc   = (const float*)d_in[3];
    const float* bc   = (const float*)d_in[4];
    const float* Wr   = (const float*)d_in[5];
    const float* br   = (const float*)d_in[6];
    int n = in_sizes[1];                 // batch_idx element count = N

    k_zero   <<<(NBATCH * NBUCK + 255) / 256, 256>>>();
    k_head   <<<1480, 256>>>(feat, bidx, coor, Wc, bc, Wr, br, n);
    k_cutoff <<<NBATCH, 256>>>();
    k_compact<<<(n + 255) / 256, 256>>>(bidx, n);
    k_sort   <<<NBATCH, 1024>>>(n);
    k_iou    <<<(NBATCH * PREK * 8 + 255) / 256, 256>>>();
    k_nms_out<<<NBATCH, 1024>>>((float*)d_out, out_size);
}

// round 4
// speedup vs baseline: 1.3659x; 1.3659x over previous
#include <cuda_runtime.h>
#include <stdint.h>
#include <math.h>

// Problem constants
#define NBATCH 4
#define PREK   1024
#define NBUCK  65536      // 16-bit buckets of float bits (scores are positive)
#define CAP    2048       // candidate capacity per batch
#define MAXN   262144     // >= 200000
#define NEGBIG (-1e9f)

// ---------------- device scratch (no allocations allowed) ----------------
__device__ float              g_raw[MAXN * 12];           // raw head outputs (11 used)
__device__ float              g_boxes[MAXN * 8];          // decoded boxes (7 used)
__device__ unsigned           g_sbits[MAXN];              // score as ordered uint
__device__ int                g_hist[NBATCH * NBUCK];     // per-batch histogram
__device__ int                g_cut[NBATCH];              // cutoff bucket
__device__ int                g_cnt[NBATCH];              // candidate counters
__device__ unsigned long long g_cand[NBATCH * CAP];       // (score_bits<<32)|(~idx)
__device__ float              g_vals[NBATCH * PREK];      // top-k scores
__device__ float              g_box7[NBATCH * PREK * 7];  // gathered boxes
__device__ float              g_x1[NBATCH * PREK], g_x2[NBATCH * PREK];
__device__ float              g_y1[NBATCH * PREK], g_y2[NBATCH * PREK];
__device__ float              g_ar[NBATCH * PREK];
__device__ unsigned           g_rows[NBATCH * PREK * 32]; // suppression bitmask rows
__device__ unsigned           g_rowAny[NBATCH * 32];      // rows with any overlap

// ---------------- K1: GEMV (1 point per warp, R1-exact reduction tree) ----
// Bitwise-identical dot products to the R1-passing kernel:
//   per-lane 8 sequential FMAs in (acc0,acc1,reg0..reg8) order,
//   then xor butterfly 16,8,4,2,1 (o-inner).
// Adds: prefetch of next point's loads (pure reorder), lane<11 select store.
// Also zeroes scratch counters (fused former k_zero).
__global__ __launch_bounds__(256) void k_gemv(
    const float* __restrict__ feat,
    const float* __restrict__ Wc, const float* __restrict__ Wr, int n)
{
    int gtid = blockIdx.x * blockDim.x + threadIdx.x;
    if (gtid < NBATCH * NBUCK) g_hist[gtid] = 0;
    if (gtid < NBATCH)         g_cnt[gtid]  = 0;
    if (gtid < NBATCH * 32)    g_rowAny[gtid] = 0;

    int lane  = threadIdx.x & 31;
    int warp  = gtid >> 5;
    int nwarp = (gridDim.x * blockDim.x) >> 5;
    int c0 = lane * 8;

    // weight slice in registers, R1 layout
    float w[11][8];
#pragma unroll
    for (int i = 0; i < 8; i++) {
        w[0][i] = Wc[(c0 + i) * 2 + 0];
        w[1][i] = Wc[(c0 + i) * 2 + 1];
#pragma unroll
        for (int o = 0; o < 9; o++) w[2 + o][i] = Wr[(c0 + i) * 9 + o];
    }

    int p = warp;
    if (p >= n) return;
    const float4* f4 = reinterpret_cast<const float4*>(feat + (size_t)p * 256);
    float4 A = f4[2 * lane];
    float4 B = f4[2 * lane + 1];

    while (p < n) {
        int pn = p + nwarp;
        float4 An, Bn;
        if (pn < n) {                     // prefetch next point's row chunk
            const float4* g4 = reinterpret_cast<const float4*>(feat + (size_t)pn * 256);
            An = g4[2 * lane];
            Bn = g4[2 * lane + 1];
        }

        float fv[8] = {A.x, A.y, A.z, A.w, B.x, B.y, B.z, B.w};
        float acc[11];
#pragma unroll
        for (int o = 0; o < 11; o++) acc[o] = 0.f;
#pragma unroll
        for (int i = 0; i < 8; i++)
#pragma unroll
            for (int o = 0; o < 11; o++) acc[o] += fv[i] * w[o][i];

#pragma unroll
        for (int off = 16; off >= 1; off >>= 1)
#pragma unroll
            for (int o = 0; o < 11; o++)
                acc[o] += __shfl_xor_sync(0xffffffffu, acc[o], off);

        // all lanes hold identical sums after xor butterfly -> select store
        float val = acc[0];
#pragma unroll
        for (int o = 1; o < 11; o++) val = (lane == o) ? acc[o] : val;
        if (lane < 11) g_raw[(size_t)p * 12 + lane] = val;

        p = pn;
        A = An; B = Bn;
    }
}

// ---------------- K1b: decode + score + histogram (thread per point) ------
__global__ __launch_bounds__(256) void k_decode(
    const int* __restrict__ bidx, const int* __restrict__ coor,
    const float* __restrict__ bc, const float* __restrict__ br, int n)
{
    int p = blockIdx.x * blockDim.x + threadIdx.x;
    if (p >= n) return;
    const float4* r4 = reinterpret_cast<const float4*>(g_raw + (size_t)p * 12);
    float4 Ra = r4[0], Rb = r4[1], Rc = r4[2];

    float l0 = Ra.x + bc[0], l1 = Ra.y + bc[1];
    float conf = 1.f / (1.f + expf(l0 - l1));
    float r0 = Ra.z + br[0], r1 = Ra.w + br[1], r2 = Rb.x + br[2];
    float r3 = Rb.y + br[3], r4v = Rb.z + br[4], r5 = Rb.w + br[5];
    float r6 = Rc.x + br[6], r7 = Rc.y + br[7], r8 = Rc.z + br[8];
    float scr = 1.f / (1.f + expf(-r8));
    float score = conf * scr;

    float cx = (float)coor[2 * p]     * 0.8f + r0;
    float cy = (float)coor[2 * p + 1] * 0.8f + r1;
    float L  = expf(fminf(fmaxf(r3,  -6.f), 6.f));
    float Wd = expf(fminf(fmaxf(r4v, -6.f), 6.f));
    float H  = expf(fminf(fmaxf(r5,  -6.f), 6.f));
    float ang = atan2f(r6, r7);

    float4* b4 = reinterpret_cast<float4*>(g_boxes + (size_t)p * 8);
    b4[0] = make_float4(cx, cy, r2, L);
    b4[1] = make_float4(Wd, H, ang, 0.f);

    unsigned sb = __float_as_uint(score);
    g_sbits[p] = sb;
    atomicAdd(&g_hist[bidx[p] * NBUCK + (sb >> 16)], 1);
}

// ---------------- K2: per-batch cutoff bucket from histogram --------------
__global__ __launch_bounds__(256) void k_cutoff() {
    int b = blockIdx.x, t = threadIdx.x;
    const int4* h4 = reinterpret_cast<const int4*>(g_hist + b * NBUCK + t * 256);
    int s = 0;
#pragma unroll 8
    for (int i = 0; i < 64; i++) { int4 v = h4[i]; s += v.x + v.y + v.z + v.w; }
    __shared__ int cs[256];
    __shared__ int Sarr[257];
    cs[t] = s;
    __syncthreads();
    int S = 0;
    for (int u = t; u < 256; u++) S += cs[u];
    Sarr[t] = S;
    if (t == 0) Sarr[256] = 0;
    __syncthreads();
    if (S >= PREK && Sarr[t + 1] < PREK) {
        int running = Sarr[t + 1];
        int cut = t * 256;
        for (int bk = t * 256 + 255; bk >= t * 256; --bk) {
            running += g_hist[b * NBUCK + bk];
            if (running >= PREK) { cut = bk; break; }
        }
        g_cut[b] = cut;
    }
    if (t == 0 && Sarr[0] < PREK) g_cut[b] = 0;
}

// ---------------- K3: compact candidates >= cutoff bucket (x4 vec) --------
__global__ void k_compact(const int* __restrict__ bidx, int n) {
    int q = blockIdx.x * blockDim.x + threadIdx.x;
    int i0 = q * 4;
    if (i0 >= n) return;
    if (i0 + 3 < n) {
        int4 bv = *reinterpret_cast<const int4*>(bidx + i0);
        uint4 sv = *reinterpret_cast<const uint4*>(g_sbits + i0);
        int bb[4] = {bv.x, bv.y, bv.z, bv.w};
        unsigned ss[4] = {sv.x, sv.y, sv.z, sv.w};
#pragma unroll
        for (int k = 0; k < 4; k++) {
            if ((int)(ss[k] >> 16) >= g_cut[bb[k]]) {
                int pos = atomicAdd(&g_cnt[bb[k]], 1);
                if (pos < CAP)
                    g_cand[bb[k] * CAP + pos] =
                        ((unsigned long long)ss[k] << 32) |
                        (unsigned long long)(0xFFFFFFFFu - (unsigned)(i0 + k));
            }
        }
    } else {
        for (int i = i0; i < n; i++) {
            int b = bidx[i];
            unsigned sb = g_sbits[i];
            if ((int)(sb >> 16) >= g_cut[b]) {
                int pos = atomicAdd(&g_cnt[b], 1);
                if (pos < CAP)
                    g_cand[b * CAP + pos] =
                        ((unsigned long long)sb << 32) |
                        (unsigned long long)(0xFFFFFFFFu - (unsigned)i);
            }
        }
    }
}

// ---------------- K4: per-batch bitonic sort + gather top-1024 ------------
__global__ __launch_bounds__(1024) void k_sort(int n) {
    __shared__ unsigned long long sk[CAP];
    int b = blockIdx.x, t = threadIdx.x;
    int cnt = g_cnt[b]; if (cnt > CAP) cnt = CAP;
#pragma unroll
    for (int r = 0; r < CAP / 1024; r++) {
        int i = t + r * 1024;
        sk[i] = (i < cnt) ? g_cand[b * CAP + i] : 0ULL;
    }
    __syncthreads();
    for (int k = 2; k <= CAP; k <<= 1) {
        for (int j = k >> 1; j > 0; j >>= 1) {
#pragma unroll
            for (int r = 0; r < CAP / 1024; r++) {
                int i = t + r * 1024;
                int l = i ^ j;
                if (l > i) {
                    unsigned long long A = sk[i], B = sk[l];
                    bool desc = ((i & k) == 0);
                    if (desc ? (A < B) : (A > B)) { sk[i] = B; sk[l] = A; }
                }
            }
            __syncthreads();
        }
    }
    if (t < PREK) {
        unsigned long long key = sk[t];
        unsigned idx = 0xFFFFFFFFu - (unsigned)(key & 0xFFFFFFFFull);
        float val = __uint_as_float((unsigned)(key >> 32));
        bool ok = (key != 0ULL) && (idx < (unsigned)n);
        float bx[7];
        if (ok) {
            const float4* p4 = reinterpret_cast<const float4*>(g_boxes + (size_t)idx * 8);
            float4 A = p4[0], B = p4[1];
            bx[0] = A.x; bx[1] = A.y; bx[2] = A.z; bx[3] = A.w;
            bx[4] = B.x; bx[5] = B.y; bx[6] = B.z;
        } else {
#pragma unroll
            for (int c = 0; c < 7; c++) bx[c] = 0.f;
            val = NEGBIG;
        }
        int o = b * PREK + t;
        g_vals[o] = val;
#pragma unroll
        for (int c = 0; c < 7; c++) g_box7[o * 7 + c] = bx[c];
        float hx = bx[3] * 0.5f, hy = bx[4] * 0.5f;
        g_x1[o] = bx[0] - hx; g_x2[o] = bx[0] + hx;
        g_y1[o] = bx[1] - hy; g_y2[o] = bx[1] + hy;
        g_ar[o] = bx[3] * bx[4];
    }
}

// ---------------- K5: suppression bitmask rows (fully parallel) -----------
__global__ void k_iou() {
    int tid = blockIdx.x * blockDim.x + threadIdx.x;
    if (tid >= NBATCH * PREK * 8) return;
    int b   = tid >> 13;
    int rem = tid & 8191;
    int i   = rem >> 3;
    int c   = rem & 7;
    int o = b * PREK;
    float x1 = g_x1[o + i], x2 = g_x2[o + i];
    float y1 = g_y1[o + i], y2 = g_y2[o + i], ar = g_ar[o + i];
    unsigned w0 = 0, w1 = 0, w2 = 0, w3 = 0;
    int j0 = c * 128;
#pragma unroll 4
    for (int jj = 0; jj < 128; jj++) {
        int j = j0 + jj;
        if (j <= i) continue;
        float ix = fmaxf(fminf(x2, g_x2[o + j]) - fmaxf(x1, g_x1[o + j]), 0.f);
        float iy = fmaxf(fminf(y2, g_y2[o + j]) - fmaxf(y1, g_y1[o + j]), 0.f);
        float inter = ix * iy;
        float uni = ar + g_ar[o + j] - inter;
        float iou = inter / fmaxf(uni, 1e-6f);
        if (iou > 0.1f) {
            unsigned bit = 1u << (jj & 31);
            if      (jj < 32) w0 |= bit;
            else if (jj < 64) w1 |= bit;
            else if (jj < 96) w2 |= bit;
            else              w3 |= bit;
        }
    }
    unsigned* rp = g_rows + ((size_t)(o + i)) * 32 + c * 4;
    rp[0] = w0; rp[1] = w1; rp[2] = w2; rp[3] = w3;
    if (w0 | w1 | w2 | w3)
        atomicOr(&g_rowAny[b * 32 + (i >> 5)], 1u << (i & 31));
}

// ---------------- K6: sparse sequential NMS scan + output -----------------
__global__ __launch_bounds__(1024) void k_nms_out(float* __restrict__ out, int out_size) {
    __shared__ unsigned supp[32];
    int b = blockIdx.x, t = threadIdx.x;
    if (t < 32) {
        unsigned sup = 0;
        unsigned myAny = g_rowAny[b * 32 + t];
        for (int w = 0; w < 32; w++) {
            unsigned aw = __shfl_sync(0xffffffffu, myAny, w);
            while (aw) {
                int bit = __ffs(aw) - 1;
                aw &= aw - 1;
                int i = w * 32 + bit;
                unsigned sw = __shfl_sync(0xffffffffu, sup, i >> 5);
                if (!((sw >> (i & 31)) & 1u))
                    sup |= g_rows[((size_t)(b * PREK + i)) * 32 + t];
            }
        }
        supp[t] = sup;
    }
    __syncthreads();
    int o = b * PREK + t;
    float val = g_vals[o];
    bool valid = val > -5e8f;
    bool kp = valid && !((supp[t >> 5] >> (t & 31)) & 1u);
    float m = kp ? 1.f : 0.f;
    size_t base = (size_t)o * 8;
#pragma unroll
    for (int c = 0; c < 7; c++)
        if ((int)(base + c) < out_size) out[base + c] = g_box7[o * 7 + c] * m;
    if ((int)(base + 7) < out_size) out[base + 7] = val * m;
    size_t lbOff = (size_t)NBATCH * PREK * 8 + o;
    if ((int)lbOff < out_size) out[lbOff] = 0.f;
    size_t kpOff = (size_t)NBATCH * PREK * 9 + o;
    if ((int)kpOff < out_size) out[kpOff] = m;
}

// ---------------- launch ----------------
extern "C" void kernel_launch(void* const* d_in, const int* in_sizes, int n_in,
                              void* d_out, int out_size) {
    const float* feat = (const float*)d_in[0];
    const int*   bidx = (const int*)  d_in[1];
    const int*   coor = (const int*)  d_in[2];
    const float* Wc   = (const float*)d_in[3];
    const float* bc   = (const float*)d_in[4];
    const float* Wr   = (const float*)d_in[5];
    const float* br   = (const float*)d_in[6];
    int n = in_sizes[1];

    k_gemv   <<<1480, 256>>>(feat, Wc, Wr, n);   // also zeroes hist/cnt/rowAny
    k_decode <<<(n + 255) / 256, 256>>>(bidx, coor, bc, br, n);
    k_cutoff <<<NBATCH, 256>>>();
    k_compact<<<((n + 3) / 4 + 255) / 256, 256>>>(bidx, n);
    k_sort   <<<NBATCH, 1024>>>(n);
    k_iou    <<<(NBATCH * PREK * 8 + 255) / 256, 256>>>();
    k_nms_out<<<NBATCH, 1024>>>((float*)d_out, out_size);
}